// round 15
// baseline (speedup 1.0000x reference)
#include <cuda_runtime.h>
#include <cuda_fp16.h>
#include <cstdint>

// ---------------- problem constants ----------------
#define B_TOT   16384
#define T_HOR   128
#define F_IN    29
#define K_HID   512
#define BTILE   64
#define NTH     256
#define NCTAS   (B_TOT / BTILE)     // 256
#define TF_STR  (T_HOR * F_IN)      // 3712 floats per batch row

// group-shared X stage: 32 rows x 15 f16x2, stride 20 u32 (conflict-free), dbl-buffered
#define XSTRIDE 20                  // u32 per row
#define XGRPU   (32 * XSTRIDE)      // 640 u32 per buffer

// ---------------- shared memory layout ----------------
#define SM_B4_OFF   0                               // 64 nt x 32 lanes x uint4 = 32KB
#define SM_B1_OFF   32768                           // 256 float2 (b1 pairs) = 2KB
#define SM_W2_OFF   (SM_B1_OFF + 2048)              // 34816: 128 x uint2 = 1KB
#define SM_PART_OFF (SM_W2_OFF + 1024)              // 35840: 2 par x 2 grp x 128 = 2KB
#define SM_X_OFF    (SM_PART_OFF + 2048)            // 37888: 2 grp x 2 buf x 640 u32
#define SM_TOTAL    (SM_X_OFF + 2 * 2 * XGRPU * 4)  // 48128 bytes (2 CTAs/SM)

static __device__ __forceinline__ uint32_t h2u(float lo, float hi) {
    uint32_t r;
    asm("cvt.rn.f16x2.f32 %0, %1, %2;" : "=r"(r) : "f"(hi), "f"(lo));
    return r;
}

static __device__ __forceinline__ uint32_t f16x2_of(float lo, float hi) {
    uint32_t r;
    asm("cvt.rn.f16x2.f32 %0, %1, %2;" : "=r"(r) : "f"(hi), "f"(lo));
    return r;
}

// packed fp16 tanh: one MUFU op for 2 elements
static __device__ __forceinline__ uint32_t tanh2(uint32_t z) {
    uint32_t h;
    asm("tanh.approx.f16x2 %0, %1;" : "=r"(h) : "r"(z));
    return h;
}

// fp32-accumulator MMA m16n8k16
#define MMA_F16(d0, d1, d2, d3, a0, a1, a2, a3, b0, b1)                        \
    asm("mma.sync.aligned.m16n8k16.row.col.f32.f16.f16.f32 "                   \
        "{%0,%1,%2,%3}, {%4,%5,%6,%7}, {%8,%9}, {%0,%1,%2,%3};"                \
        : "+f"(d0), "+f"(d1), "+f"(d2), "+f"(d3)                               \
        : "r"(a0), "r"(a1), "r"(a2), "r"(a3), "r"(b0), "r"(b1))

// group barrier: 4 warps = 128 threads, ids 1..2 per CTA
#define BAR_GRP(id) asm volatile("bar.sync %0, 128;" :: "r"(id) : "memory")

__global__ void __launch_bounds__(NTH, 2)
narx_kernel(const float* __restrict__ X, const float* __restrict__ y0,
            const float* __restrict__ W1, const float* __restrict__ b1,
            const float* __restrict__ W2, const float* __restrict__ b2,
            float* __restrict__ out)
{
    extern __shared__ char smem[];
    uint4*    __restrict__ B4   = (uint4*)(smem + SM_B4_OFF);
    float2*   __restrict__ b1sm = (float2*)(smem + SM_B1_OFF);
    uint2*    __restrict__ w2sm = (uint2*)(smem + SM_W2_OFF);
    float*    __restrict__ part = (float*)(smem + SM_PART_OFF);

    const int tid  = threadIdx.x;
    const int w    = tid >> 5;
    const int lane = tid & 31;
    const int lq   = lane & 3;       // quad lane
    const int lg   = lane >> 2;      // group (row selector 0..7)
    const int rg   = w & 1;          // row group: rows rg*32 .. rg*32+31
    const int q    = w >> 1;         // column quarter: cols q*128 .. q*128+127
    const int ctaB0 = blockIdx.x * BTILE;

    uint32_t* __restrict__ Xgrp = (uint32_t*)(smem + SM_X_OFF) + rg * (2 * XGRPU);

    // --- stage B (W1, all 32 rows) as fp16 ---
    for (int idx = tid; idx < 2048; idx += NTH) {
        const int lnt = idx & 31;
        const int col = (idx >> 5) * 8 + (lnt >> 2);
        const int kk = (lnt & 3) * 2;
        uint4 bv;
        bv.x = h2u(W1[kk * K_HID + col],        W1[(kk + 1) * K_HID + col]);
        bv.y = h2u(W1[(kk + 8) * K_HID + col],  W1[(kk + 9) * K_HID + col]);
        bv.z = h2u(W1[(kk + 16) * K_HID + col], W1[(kk + 17) * K_HID + col]);
        bv.w = h2u(W1[(kk + 24) * K_HID + col], W1[(kk + 25) * K_HID + col]);
        B4[idx] = bv;
    }
    // --- b1 col-pair constants (fp32 for accum init) ---
    for (int p = tid; p < K_HID / 2; p += NTH) {
        float2 c;
        c.x = b1[2 * p];
        c.y = b1[2 * p + 1];
        b1sm[p] = c;
    }
    // --- W2 as f16x2 B-fragments for the dot-MMA ---
    for (int idx = tid; idx < 128; idx += NTH) {
        const int lqt = idx & 3, ntp = (idx >> 2) & 7, qq = idx >> 5;
        const int C = qq * 128 + ntp * 16;
        uint2 v;
        v.x = h2u(W2[C + 2 * lqt],     W2[C + 2 * lqt + 1]);
        v.y = h2u(W2[C + 2 * lqt + 8], W2[C + 2 * lqt + 9]);
        w2sm[idx] = v;
    }

    // --- X staging: group covers 32 rows x 15 u32 = 480; warp q stages [q*120, q*120+120) ---
    const float* __restrict__ Xbase = X + (size_t)(ctaB0 + rg * 32) * TF_STR;
    const int jBase = q * 120;

    #pragma unroll
    for (int k = 0; k < 4; ++k) {
        if (lane + k * 32 < 120) {
            const int j = jBase + lane + k * 32;
            const int row = j / 15, p = j - row * 15;
            const float* src = Xbase + (size_t)row * TF_STR;
            const float lo = __ldg(src + 2 * p);
            const float hi = (p < 14) ? __ldg(src + 2 * p + 1) : 0.0f;
            Xgrp[row * XSTRIDE + p] = h2u(lo, hi);
        }
    }
    __syncthreads();

    // --- per-thread rows: rowG+0/+8 (set0), rowG+16/+24 (set1) ---
    const int rowG = ctaB0 + rg * 32 + lg;
    float* __restrict__ outBase = out + (size_t)rowG * T_HOR;

    const float b2v = b2[0];
    const int barId = 1 + rg;

    float f0a = y0[rowG * 3 + 0];
    float f0b = y0[(rowG + 8) * 3 + 0];
    float f0c = y0[(rowG + 16) * 3 + 0];
    float f0d = y0[(rowG + 24) * 3 + 0];
    uint32_t fb0aH = h2u(0.0f, f0a), fb0bH = h2u(0.0f, f0b);
    uint32_t fb0cH = h2u(0.0f, f0c), fb0dH = h2u(0.0f, f0d);
    uint32_t fb12a = h2u(y0[rowG * 3 + 1],        y0[rowG * 3 + 2]);
    uint32_t fb12b = h2u(y0[(rowG + 8) * 3 + 1],  y0[(rowG + 8) * 3 + 2]);
    uint32_t fb12c = h2u(y0[(rowG + 16) * 3 + 1], y0[(rowG + 16) * 3 + 2]);
    uint32_t fb12d = h2u(y0[(rowG + 24) * 3 + 1], y0[(rowG + 24) * 3 + 2]);

    const int ntOfs = q * 16;            // this warp's 16 n-tiles (128 cols)
    const int w2Base = q * 32;           // uint2 index base: q*32 + ntp*4 + lq

    for (int t = 0; t < T_HOR; ++t) {
        const uint32_t* Xp = Xgrp + (t & 1) * XGRPU;

        // A fragments for both row sets: 16 LDS.32, zero cvts
        const uint32_t* xA = Xp + lg * XSTRIDE;
        const uint32_t* xB = xA + 8 * XSTRIDE;
        const uint32_t* xC = xA + 16 * XSTRIDE;
        const uint32_t* xD = xA + 24 * XSTRIDE;
        uint32_t a0[8], a1[8];
        a0[0] = xA[lq];     a0[1] = xB[lq];
        a0[2] = xA[lq + 4]; a0[3] = xB[lq + 4];
        a0[4] = xA[lq + 8]; a0[5] = xB[lq + 8];
        a1[0] = xC[lq];     a1[1] = xD[lq];
        a1[2] = xC[lq + 4]; a1[3] = xD[lq + 4];
        a1[4] = xC[lq + 8]; a1[5] = xD[lq + 8];
        if (lq < 2) {
            a0[6] = xA[lq + 12];  a0[7] = xB[lq + 12];
            a1[6] = xC[lq + 12];  a1[7] = xD[lq + 12];
        } else if (lq == 2) {
            a0[6] = (xA[14] & 0xFFFFu) | fb0aH;   // (x28, fb0)
            a0[7] = (xB[14] & 0xFFFFu) | fb0bH;
            a1[6] = (xC[14] & 0xFFFFu) | fb0cH;
            a1[7] = (xD[14] & 0xFFFFu) | fb0dH;
        } else {
            a0[6] = fb12a;  a0[7] = fb12b;        // (fb1, fb2)
            a1[6] = fb12c;  a1[7] = fb12d;
        }

        // prefetch this warp's share of X(t+1), packed (off critical path)
        uint32_t xr[4];
        const bool pf = (t + 1) < T_HOR;
        if (pf) {
            const float* __restrict__ src = Xbase + (size_t)(t + 1) * F_IN;
            #pragma unroll
            for (int k = 0; k < 4; ++k) {
                if (lane + k * 32 < 120) {
                    const int j = jBase + lane + k * 32;
                    const int row = j / 15, p = j - row * 15;
                    const float lo = __ldg(src + (size_t)row * TF_STR + 2 * p);
                    const float hi = (p < 14) ? __ldg(src + (size_t)row * TF_STR + 2 * p + 1) : 0.0f;
                    xr[k] = h2u(lo, hi);
                }
            }
        }

        // dot accumulators for both row sets (n=0 lands in lq==0's d0/d2)
        float dt0 = 0.0f, dt1 = 0.0f, dt2 = 0.0f, dt3 = 0.0f;
        float et0 = 0.0f, et1 = 0.0f, et2 = 0.0f, et3 = 0.0f;

        #pragma unroll 2
        for (int ntp = 0; ntp < 8; ++ntp) {
            uint32_t g0lo, g0hi, g1lo, g1hi;   // set0 h tiles (e=0, e=1)
            uint32_t k0lo, k0hi, k1lo, k1hi;   // set1 h tiles
            #pragma unroll
            for (int e = 0; e < 2; ++e) {
                const int ntg = ntOfs + 2 * ntp + e;
                const float2 bb1 = b1sm[ntg * 4 + lq];
                const uint4 bv = B4[ntg * 32 + lane];
                float d0 = bb1.x, d1 = bb1.y, d2 = bb1.x, d3 = bb1.y;  // set0
                float e0 = bb1.x, e1 = bb1.y, e2 = bb1.x, e3 = bb1.y;  // set1
                MMA_F16(d0, d1, d2, d3, a0[0], a0[1], a0[2], a0[3], bv.x, bv.y);
                MMA_F16(e0, e1, e2, e3, a1[0], a1[1], a1[2], a1[3], bv.x, bv.y);
                MMA_F16(d0, d1, d2, d3, a0[4], a0[5], a0[6], a0[7], bv.z, bv.w);
                MMA_F16(e0, e1, e2, e3, a1[4], a1[5], a1[6], a1[7], bv.z, bv.w);
                const uint32_t hlo = tanh2(f16x2_of(d0, d1));
                const uint32_t hhi = tanh2(f16x2_of(d2, d3));
                const uint32_t klo = tanh2(f16x2_of(e0, e1));
                const uint32_t khi = tanh2(f16x2_of(e2, e3));
                if (e == 0) { g0lo = hlo; g0hi = hhi; k0lo = klo; k0hi = khi; }
                else        { g1lo = hlo; g1hi = hhi; k1lo = klo; k1hi = khi; }
            }
            // dot-MMAs: B = w2 in column n=0 (lg==0 lanes)
            uint32_t w0 = 0, w1 = 0;
            if (lg == 0) {
                const uint2 wv = w2sm[w2Base + ntp * 4 + lq];
                w0 = wv.x; w1 = wv.y;
            }
            MMA_F16(dt0, dt1, dt2, dt3, g0lo, g0hi, g1lo, g1hi, w0, w1);
            MMA_F16(et0, et1, et2, et3, k0lo, k0hi, k1lo, k1hi, w0, w1);
        }

        // store staged X(t+1) (fenced by the group barrier below)
        if (pf) {
            uint32_t* __restrict__ Xn = Xgrp + ((t + 1) & 1) * XGRPU;
            #pragma unroll
            for (int k = 0; k < 4; ++k) {
                if (lane + k * 32 < 120) {
                    const int j = jBase + lane + k * 32;
                    const int row = j / 15, p = j - row * 15;
                    Xn[row * XSTRIDE + p] = xr[k];
                }
            }
        }

        // exchange quarter-dots within the 4-warp group
        float* pbuf = part + (t & 1) * 256 + rg * 128;
        if (lq == 0) {
            pbuf[q * 32 + lg]      = dt0;   // row lg
            pbuf[q * 32 + lg + 8]  = dt2;   // row lg+8
            pbuf[q * 32 + lg + 16] = et0;   // row lg+16
            pbuf[q * 32 + lg + 24] = et2;   // row lg+24
        }
        BAR_GRP(barId);     // drains STS (partials AND X(t+1)); syncs the 4-warp group

        const float predA = pbuf[lg]      + pbuf[32 + lg]      + pbuf[64 + lg]      + pbuf[96 + lg]      + b2v;
        const float predB = pbuf[lg + 8]  + pbuf[32 + lg + 8]  + pbuf[64 + lg + 8]  + pbuf[96 + lg + 8]  + b2v;
        const float predC = pbuf[lg + 16] + pbuf[32 + lg + 16] + pbuf[64 + lg + 16] + pbuf[96 + lg + 16] + b2v;
        const float predD = pbuf[lg + 24] + pbuf[32 + lg + 24] + pbuf[64 + lg + 24] + pbuf[96 + lg + 24] + b2v;
        if (q == 0 && lq == 0) {
            outBase[t]              = predA;
            outBase[8 * T_HOR + t]  = predB;
            outBase[16 * T_HOR + t] = predC;
            outBase[24 * T_HOR + t] = predD;
        }
        // shift feedback: fb2 <- fb1 <- fb0 <- pred (packed repack, proven in R14)
        fb12a = (fb0aH >> 16) | (fb12a << 16);
        fb12b = (fb0bH >> 16) | (fb12b << 16);
        fb12c = (fb0cH >> 16) | (fb12c << 16);
        fb12d = (fb0dH >> 16) | (fb12d << 16);
        fb0aH = h2u(0.0f, predA);
        fb0bH = h2u(0.0f, predB);
        fb0cH = h2u(0.0f, predC);
        fb0dH = h2u(0.0f, predD);
    }
}

extern "C" void kernel_launch(void* const* d_in, const int* in_sizes, int n_in,
                              void* d_out, int out_size) {
    const float* X  = (const float*)d_in[0];
    const float* y0 = (const float*)d_in[1];
    const float* W1 = (const float*)d_in[2];
    const float* b1 = (const float*)d_in[3];
    const float* W2 = (const float*)d_in[4];
    const float* b2 = (const float*)d_in[5];
    float* out = (float*)d_out;
    (void)in_sizes; (void)n_in; (void)out_size;

    cudaFuncSetAttribute(narx_kernel, cudaFuncAttributeMaxDynamicSharedMemorySize, SM_TOTAL);
    narx_kernel<<<NCTAS, NTH, SM_TOTAL>>>(X, y0, W1, b1, W2, b2, out);
}

// round 16
// speedup vs baseline: 1.0329x; 1.0329x over previous
#include <cuda_runtime.h>
#include <cuda_fp16.h>
#include <cstdint>

// ---------------- problem constants ----------------
#define B_TOT   16384
#define T_HOR   128
#define F_IN    29
#define K_HID   512
#define BTILE   64
#define NTH     256
#define NCTAS   (B_TOT / BTILE)     // 256
#define TF_STR  (T_HOR * F_IN)      // 3712 floats per batch row

// pair-shared X stage: 16 rows x 15 f16x2, stride 20 u32 (conflict-free), dbl-buffered
#define XSTRIDE 20                  // u32 per row
#define XPAIRU  (16 * XSTRIDE)      // 320 u32 per buffer

// ---------------- shared memory layout ----------------
#define SM_B4_OFF   0                               // 64 nt x 32 lanes x uint4 = 32KB
#define SM_B1_OFF   32768                           // 256 float2 (b1 pairs) = 2KB
#define SM_W2_OFF   (SM_B1_OFF + 2048)              // 34816: 128 x uint2 = 1KB
#define SM_PART_OFF (SM_W2_OFF + 1024)              // 35840: 2 x 128 floats = 1KB
#define SM_X_OFF    (SM_PART_OFF + 1024)            // 36864: 4 pairs x 2 x 320 u32
#define SM_TOTAL    (SM_X_OFF + 4 * 2 * XPAIRU * 4) // 47104 bytes (2 CTAs/SM)

static __device__ __forceinline__ uint32_t h2u(float lo, float hi) {
    uint32_t r;
    asm("cvt.rn.f16x2.f32 %0, %1, %2;" : "=r"(r) : "f"(hi), "f"(lo));
    return r;
}

// packed fp16 tanh: one MUFU op for 2 elements
static __device__ __forceinline__ uint32_t tanh2(uint32_t z) {
    uint32_t h;
    asm("tanh.approx.f16x2 %0, %1;" : "=r"(h) : "r"(z));
    return h;
}

// fp32-accumulator MMA m16n8k16
#define MMA_F16(d0, d1, d2, d3, a0, a1, a2, a3, b0, b1)                        \
    asm("mma.sync.aligned.m16n8k16.row.col.f32.f16.f16.f32 "                   \
        "{%0,%1,%2,%3}, {%4,%5,%6,%7}, {%8,%9}, {%0,%1,%2,%3};"                \
        : "+f"(d0), "+f"(d1), "+f"(d2), "+f"(d3)                               \
        : "r"(a0), "r"(a1), "r"(a2), "r"(a3), "r"(b0), "r"(b1))

// pairwise named barrier: 2 warps = 64 threads
#define BAR_PAIR(id) asm volatile("bar.sync %0, 64;" :: "r"(id) : "memory")

__global__ void __launch_bounds__(NTH, 2)
narx_kernel(const float* __restrict__ X, const float* __restrict__ y0,
            const float* __restrict__ W1, const float* __restrict__ b1,
            const float* __restrict__ W2, const float* __restrict__ b2,
            float* __restrict__ out)
{
    extern __shared__ char smem[];
    uint4*    __restrict__ B4   = (uint4*)(smem + SM_B4_OFF);
    float2*   __restrict__ b1sm = (float2*)(smem + SM_B1_OFF);
    uint2*    __restrict__ w2sm = (uint2*)(smem + SM_W2_OFF);
    float*    __restrict__ part = (float*)(smem + SM_PART_OFF);

    const int tid  = threadIdx.x;
    const int w    = tid >> 5;
    const int lane = tid & 31;
    const int lq   = lane & 3;       // quad lane
    const int lg   = lane >> 2;      // group (row selector 0..7)
    const int pr   = w >> 1;         // pair index 0..3
    const int h    = w & 1;          // column half: cols h*256 .. h*256+255
    const int ctaB0 = blockIdx.x * BTILE;

    uint32_t* __restrict__ Xpair = (uint32_t*)(smem + SM_X_OFF) + pr * (2 * XPAIRU);

    // --- stage B (W1, all 32 rows) as fp16 ---
    for (int idx = tid; idx < 2048; idx += NTH) {
        const int lnt = idx & 31;
        const int col = (idx >> 5) * 8 + (lnt >> 2);
        const int kk = (lnt & 3) * 2;
        uint4 bv;
        bv.x = h2u(W1[kk * K_HID + col],        W1[(kk + 1) * K_HID + col]);
        bv.y = h2u(W1[(kk + 8) * K_HID + col],  W1[(kk + 9) * K_HID + col]);
        bv.z = h2u(W1[(kk + 16) * K_HID + col], W1[(kk + 17) * K_HID + col]);
        bv.w = h2u(W1[(kk + 24) * K_HID + col], W1[(kk + 25) * K_HID + col]);
        B4[idx] = bv;
    }
    // --- b1 col-pair constants (fp32 accum init) ---
    for (int p = tid; p < K_HID / 2; p += NTH) {
        float2 c;
        c.x = b1[2 * p];
        c.y = b1[2 * p + 1];
        b1sm[p] = c;
    }
    // --- W2 as f16x2 B-fragments for the dot-MMA ---
    for (int idx = tid; idx < 128; idx += NTH) {
        const int lqt = idx & 3, ntp = (idx >> 2) & 15, hh = idx >> 6;
        const int C = (hh * 32 + 2 * ntp) * 8;
        uint2 v;
        v.x = h2u(W2[C + 2 * lqt],     W2[C + 2 * lqt + 1]);
        v.y = h2u(W2[C + 2 * lqt + 8], W2[C + 2 * lqt + 9]);
        w2sm[idx] = v;
    }

    // --- X staging (packed f16x2): pair covers 16 rows x 15 u32 = 240,
    //     warp h stages elements [h*120, h*120+120) ---
    const float* __restrict__ Xbase = X + (size_t)(ctaB0 + pr * 16) * TF_STR;
    const int jBase = h * 120;

    #pragma unroll
    for (int k = 0; k < 4; ++k) {
        if (lane + k * 32 < 120) {
            const int j = jBase + lane + k * 32;
            const int row = j / 15, p = j - row * 15;
            const float* src = Xbase + (size_t)row * TF_STR;
            const float lo = __ldg(src + 2 * p);
            const float hi = (p < 14) ? __ldg(src + 2 * p + 1) : 0.0f;
            Xpair[row * XSTRIDE + p] = h2u(lo, hi);
        }
    }
    __syncthreads();

    // --- per-thread rows: rowG (lg) and rowG+8 ---
    const int rowG = ctaB0 + pr * 16 + lg;
    float* __restrict__ outA = out + (size_t)rowG * T_HOR;
    float* __restrict__ outB = outA + 8 * T_HOR;

    const float b2v = b2[0];
    const int barId = 1 + pr;
    const int pBase = pr * 32;

    // packed feedback: fb0 in HIGH half (pairs with x28 lo); (fb1,fb2) full pair
    uint32_t fb0aH = h2u(0.0f, y0[rowG * 3 + 0]);
    uint32_t fb0bH = h2u(0.0f, y0[(rowG + 8) * 3 + 0]);
    uint32_t fb12a = h2u(y0[rowG * 3 + 1],       y0[rowG * 3 + 2]);
    uint32_t fb12b = h2u(y0[(rowG + 8) * 3 + 1], y0[(rowG + 8) * 3 + 2]);

    const int ntOfs = h * 32;            // this warp's 32 n-tiles (256 cols)
    const int w2Base = h * 64;

    for (int t = 0; t < T_HOR; ++t) {
        const uint32_t* Xp = Xpair + (t & 1) * XPAIRU;

        // A fragments: 8 LDS.32 + 2 LOPs, zero cvts
        const uint32_t* xA = Xp + lg * XSTRIDE;
        const uint32_t* xB = xA + 8 * XSTRIDE;
        uint32_t a[8];
        a[0] = xA[lq];      a[1] = xB[lq];
        a[2] = xA[lq + 4];  a[3] = xB[lq + 4];
        a[4] = xA[lq + 8];  a[5] = xB[lq + 8];
        if (lq < 2) {
            a[6] = xA[lq + 12];
            a[7] = xB[lq + 12];
        } else if (lq == 2) {
            a[6] = (xA[14] & 0xFFFFu) | fb0aH;   // (x28, fb0)
            a[7] = (xB[14] & 0xFFFFu) | fb0bH;
        } else {
            a[6] = fb12a;                         // (fb1, fb2)
            a[7] = fb12b;
        }

        // prefetch this warp's share of X(t+1), packed at load time (off critical path)
        uint32_t xr[4];
        const bool pf = (t + 1) < T_HOR;
        if (pf) {
            const float* __restrict__ src = Xbase + (size_t)(t + 1) * F_IN;
            #pragma unroll
            for (int k = 0; k < 4; ++k) {
                if (lane + k * 32 < 120) {
                    const int j = jBase + lane + k * 32;
                    const int row = j / 15, p = j - row * 15;
                    const float lo = __ldg(src + (size_t)row * TF_STR + 2 * p);
                    const float hi = (p < 14) ? __ldg(src + (size_t)row * TF_STR + 2 * p + 1) : 0.0f;
                    xr[k] = h2u(lo, hi);
                }
            }
        }

        // dot accumulators (fp32, via dot-MMA); n=0 result lands in lq==0's dt0/dt2
        float dt0 = 0.0f, dt1 = 0.0f, dt2 = 0.0f, dt3 = 0.0f;

        #pragma unroll
        for (int ntp = 0; ntp < 16; ++ntp) {
            uint32_t hlo0, hhi0, hlo1, hhi1;
            #pragma unroll
            for (int e = 0; e < 2; ++e) {
                const int ntg = ntOfs + 2 * ntp + e;
                const float2 bb1 = b1sm[ntg * 4 + lq];
                const uint4 bv = B4[ntg * 32 + lane];
                float d0 = bb1.x, d1 = bb1.y, d2 = bb1.x, d3 = bb1.y;  // bias-init
                MMA_F16(d0, d1, d2, d3, a[0], a[1], a[2], a[3], bv.x, bv.y);
                MMA_F16(d0, d1, d2, d3, a[4], a[5], a[6], a[7], bv.z, bv.w);
                const uint32_t hlo = tanh2(h2u(d0, d1));   // rows lg,   cols c0,c1
                const uint32_t hhi = tanh2(h2u(d2, d3));   // rows lg+8, cols c0,c1
                if (e == 0) { hlo0 = hlo; hhi0 = hhi; }
                else        { hlo1 = hlo; hhi1 = hhi; }
            }
            // dot-MMA: A = h tile, B = w2 in n=0 (lg==0 lanes), fp32 D accum
            uint32_t w0 = 0, w1 = 0;
            if (lg == 0) {
                const uint2 wv = w2sm[w2Base + ntp * 4 + lq];
                w0 = wv.x; w1 = wv.y;
            }
            MMA_F16(dt0, dt1, dt2, dt3, hlo0, hhi0, hlo1, hhi1, w0, w1);
        }

        // store staged X(t+1) into the other buffer (fenced by BAR below)
        if (pf) {
            uint32_t* __restrict__ Xn = Xpair + ((t + 1) & 1) * XPAIRU;
            #pragma unroll
            for (int k = 0; k < 4; ++k) {
                if (lane + k * 32 < 120) {
                    const int j = jBase + lane + k * 32;
                    const int row = j / 15, p = j - row * 15;
                    Xn[row * XSTRIDE + p] = xr[k];
                }
            }
        }

        // exchange half-dots with the paired warp
        float* pbuf = part + (t & 1) * 128;
        if (lq == 0) {
            pbuf[pBase + h * 16 + lg]     = dt0;   // rows lg
            pbuf[pBase + h * 16 + lg + 8] = dt2;   // rows lg+8
        }
        BAR_PAIR(barId);    // drains STS (partials AND X(t+1)); syncs only the pair

        const float predA = pbuf[pBase + lg]     + pbuf[pBase + 16 + lg]     + b2v;
        const float predB = pbuf[pBase + lg + 8] + pbuf[pBase + 16 + lg + 8] + b2v;
        if (h == 0 && lq == 0) {
            outA[t] = predA;
            outB[t] = predB;
        }
        // shift feedback: fb2 <- fb1 <- fb0 <- pred (packed repack)
        fb12a = (fb0aH >> 16) | (fb12a << 16);     // (fb0_old, fb1_old)
        fb12b = (fb0bH >> 16) | (fb12b << 16);
        fb0aH = h2u(0.0f, predA);
        fb0bH = h2u(0.0f, predB);
    }
}

extern "C" void kernel_launch(void* const* d_in, const int* in_sizes, int n_in,
                              void* d_out, int out_size) {
    const float* X  = (const float*)d_in[0];
    const float* y0 = (const float*)d_in[1];
    const float* W1 = (const float*)d_in[2];
    const float* b1 = (const float*)d_in[3];
    const float* W2 = (const float*)d_in[4];
    const float* b2 = (const float*)d_in[5];
    float* out = (float*)d_out;
    (void)in_sizes; (void)n_in; (void)out_size;

    cudaFuncSetAttribute(narx_kernel, cudaFuncAttributeMaxDynamicSharedMemorySize, SM_TOTAL);
    narx_kernel<<<NCTAS, NTH, SM_TOTAL>>>(X, y0, W1, b1, W2, b2, out);
}